// round 2
// baseline (speedup 1.0000x reference)
#include <cuda_runtime.h>
#include <math.h>

#define Bsz 65536
#define Dd  256
#define Hh  256
#define Kk  11
#define TM  64
#define PAD 257
#define KT  32

// Scratch (no cudaMalloc allowed): encoder outputs
__device__ float g_z [(size_t)Bsz * Hh];            // z  = enc(x)        [B,H]
__device__ float g_zt[(size_t)Kk * Bsz * Hh];       // zt = enc(tx_k)     [K,B,H]

// ---------- packed f32x2 helpers (sm_100+: fma.rn.f32x2) ----------
__device__ __forceinline__ unsigned long long pack2(float a, float b) {
    unsigned long long r;
    asm("mov.b64 %0, {%1, %2};" : "=l"(r) : "f"(a), "f"(b));
    return r;
}
__device__ __forceinline__ unsigned long long fma2(unsigned long long a,
                                                   unsigned long long b,
                                                   unsigned long long c) {
    unsigned long long d;
    asm("fma.rn.f32x2 %0, %1, %2, %3;" : "=l"(d) : "l"(a), "l"(b), "l"(c));
    return d;
}
__device__ __forceinline__ void unpack2(unsigned long long v, float& lo, float& hi) {
    asm("mov.b64 {%0, %1}, %2;" : "=f"(lo), "=f"(hi) : "l"(v));
}

__device__ __forceinline__ float gelu_exact(float v) {
    return 0.5f * v * (1.0f + erff(v * 0.70710678118654752440f));
}

// One dense layer: sout[r][c] = act( sum_kk sin_[r][kk] * W[kk][c] + b[c] )
// sin_/sout: SMEM tiles [TM][PAD]; W: global [256][256] row-major (reduction-major);
// ws: SMEM staging [KT][256].
__device__ __forceinline__ void mlp_layer(
    const float* __restrict__ gW, const float* __restrict__ gb,
    const float* sin_, float* sout, float* ws, bool do_gelu)
{
    const int tid = threadIdx.x;
    const int tx  = tid & 15;   // 16 col-groups
    const int ty  = tid >> 4;   // 16 row-groups

    unsigned long long acc[4][8];
#pragma unroll
    for (int i = 0; i < 4; i++)
#pragma unroll
        for (int j = 0; j < 8; j++) acc[i][j] = 0ull;

    for (int kt = 0; kt < Dd; kt += KT) {
        __syncthreads();  // ws reuse guard (also orders producer writes of sin_)
        const float4* src = (const float4*)(gW + (size_t)kt * Hh);
        float4* dst = (float4*)ws;
#pragma unroll
        for (int i = 0; i < 8; i++) dst[tid + i * 256] = src[tid + i * 256];
        __syncthreads();

#pragma unroll
        for (int kk = 0; kk < KT; kk++) {
            unsigned long long a2[4];
#pragma unroll
            for (int i = 0; i < 4; i++) {
                float a = sin_[(ty + 16 * i) * PAD + kt + kk];
                a2[i] = pack2(a, a);
            }
#pragma unroll
            for (int j = 0; j < 8; j++) {
                unsigned long long w2 =
                    *(const unsigned long long*)(ws + kk * Hh + 2 * tx + 32 * j);
#pragma unroll
                for (int i = 0; i < 4; i++) acc[i][j] = fma2(a2[i], w2, acc[i][j]);
            }
        }
    }
    __syncthreads();

#pragma unroll
    for (int j = 0; j < 8; j++) {
        int c = 2 * tx + 32 * j;
        float b0 = __ldg(gb + c), b1 = __ldg(gb + c + 1);
#pragma unroll
        for (int i = 0; i < 4; i++) {
            float lo, hi;
            unpack2(acc[i][j], lo, hi);
            lo += b0; hi += b1;
            if (do_gelu) { lo = gelu_exact(lo); hi = gelu_exact(hi); }
            int r = ty + 16 * i;
            sout[r * PAD + c]     = lo;
            sout[r * PAD + c + 1] = hi;
        }
    }
}

// FOUR=true : zt_k = enc( gelu(x@Tw1_k+b1)@Tw2_k+b2 )   -> g_zt[k]
// FOUR=false: z    = enc( x )                            -> g_z
template <bool FOUR>
__global__ void __launch_bounds__(256, 1) chain_kernel(
    const float* __restrict__ x,
    const float* __restrict__ Tw1, const float* __restrict__ Tb1,
    const float* __restrict__ Tw2, const float* __restrict__ Tb2,
    const float* __restrict__ Ew1, const float* __restrict__ Eb1,
    const float* __restrict__ Ew2, const float* __restrict__ Eb2)
{
    extern __shared__ float smem[];
    float* bufA = smem;
    float* bufB = smem + TM * PAD;
    float* ws   = smem + 2 * TM * PAD;

    const int    k    = FOUR ? blockIdx.y : 0;
    const size_t row0 = (size_t)blockIdx.x * TM;

    // Load 64x256 input tile (coalesced float4) into bufA
    const float4* gx = (const float4*)(x + row0 * Dd);
    for (int i = threadIdx.x; i < TM * (Dd / 4); i += 256) {
        int r = i >> 6, c4 = i & 63;
        float4 v = gx[(size_t)r * 64 + c4];
        float* d = &bufA[r * PAD + c4 * 4];
        d[0] = v.x; d[1] = v.y; d[2] = v.z; d[3] = v.w;
    }

    if constexpr (FOUR) {
        mlp_layer(Tw1 + (size_t)k * Dd * Hh, Tb1 + k * Hh, bufA, bufB, ws, true);
        mlp_layer(Tw2 + (size_t)k * Hh * Dd, Tb2 + k * Dd, bufB, bufA, ws, false);
        mlp_layer(Ew1, Eb1, bufA, bufB, ws, true);
        mlp_layer(Ew2, Eb2, bufB, bufA, ws, false);
    } else {
        mlp_layer(Ew1, Eb1, bufA, bufB, ws, true);
        mlp_layer(Ew2, Eb2, bufB, bufA, ws, false);
    }
    __syncthreads();

    float* gout = FOUR ? (g_zt + ((size_t)k * Bsz + row0) * Hh)
                       : (g_z + row0 * Hh);
    for (int i = threadIdx.x; i < TM * Hh; i += 256) {
        int r = i >> 8, c = i & 255;
        gout[(size_t)r * Hh + c] = bufA[r * PAD + c];
    }
}

// Pairwise cosine-sim scoring: 1 warp per sample.
__global__ void __launch_bounds__(256) score_kernel(float* __restrict__ out)
{
    const int warp = threadIdx.x >> 5;
    const int lane = threadIdx.x & 31;
    const size_t b = (size_t)blockIdx.x * 8 + warp;

    // vec 0 = z, vec 1+k = zt_k; lane holds elements [lane*8, lane*8+8)
    float v[12][8];
    {
        const float4* p = (const float4*)(g_z + b * Hh) + lane * 2;
        float4 u0 = p[0], u1 = p[1];
        v[0][0]=u0.x; v[0][1]=u0.y; v[0][2]=u0.z; v[0][3]=u0.w;
        v[0][4]=u1.x; v[0][5]=u1.y; v[0][6]=u1.z; v[0][7]=u1.w;
    }
#pragma unroll
    for (int k = 0; k < Kk; k++) {
        const float4* p = (const float4*)(g_zt + ((size_t)k * Bsz + b) * Hh) + lane * 2;
        float4 u0 = p[0], u1 = p[1];
        v[1+k][0]=u0.x; v[1+k][1]=u0.y; v[1+k][2]=u0.z; v[1+k][3]=u0.w;
        v[1+k][4]=u1.x; v[1+k][5]=u1.y; v[1+k][6]=u1.z; v[1+k][7]=u1.w;
    }

    __shared__ float dots[8][80];  // 78 pair-dots per warp
    int idx = 0;
#pragma unroll
    for (int p = 0; p < 12; p++) {
#pragma unroll
        for (int q = p; q < 12; q++) {
            float s = 0.f;
#pragma unroll
            for (int e = 0; e < 8; e++) s += v[p][e] * v[q][e];
#pragma unroll
            for (int off = 16; off; off >>= 1)
                s += __shfl_xor_sync(0xffffffffu, s, off);
            if (lane == 0) dots[warp][idx] = s;
            idx++;
        }
    }
    __syncwarp();

    auto pidx = [](int p, int q) {
        if (p > q) { int t = p; p = q; q = t; }
        return p * 12 - p * (p + 1) / 2 + q;
    };

    float score = 0.f;
    if (lane < Kk) {
        const float* d = dots[warp];
        int kv = 1 + lane;
        float nz = sqrtf(d[pidx(0, 0)]);
        float nk = sqrtf(d[pidx(kv, kv)]);
        float simz = expf(d[pidx(0, kv)] / fmaxf(nz * nk, 1e-8f));
        float neg = 0.f;
        for (int l = 0; l < Kk; l++) {
            if (l == lane) continue;
            int lv = 1 + l;
            float nl = sqrtf(d[pidx(lv, lv)]);
            neg += expf(d[pidx(lv, kv)] / fmaxf(nl * nk, 1e-8f));
        }
        score = logf(simz / (simz + neg));
    }
#pragma unroll
    for (int off = 16; off; off >>= 1)
        score += __shfl_xor_sync(0xffffffffu, score, off);
    if (lane == 0) out[b] = -score;
}

extern "C" void kernel_launch(void* const* d_in, const int* in_sizes, int n_in,
                              void* d_out, int out_size)
{
    const float* x   = (const float*)d_in[0];
    const float* Tw1 = (const float*)d_in[1];
    const float* Tb1 = (const float*)d_in[2];
    const float* Tw2 = (const float*)d_in[3];
    const float* Tb2 = (const float*)d_in[4];
    const float* Ew1 = (const float*)d_in[5];
    const float* Eb1 = (const float*)d_in[6];
    const float* Ew2 = (const float*)d_in[7];
    const float* Eb2 = (const float*)d_in[8];

    const int smem_bytes = (2 * TM * PAD + KT * Hh) * sizeof(float);  // ~160.5 KB
    cudaFuncSetAttribute(chain_kernel<true>,
                         cudaFuncAttributeMaxDynamicSharedMemorySize, smem_bytes);
    cudaFuncSetAttribute(chain_kernel<false>,
                         cudaFuncAttributeMaxDynamicSharedMemorySize, smem_bytes);

    chain_kernel<false><<<Bsz / TM, 256, smem_bytes>>>(
        x, nullptr, nullptr, nullptr, nullptr, Ew1, Eb1, Ew2, Eb2);
    chain_kernel<true><<<dim3(Bsz / TM, Kk), 256, smem_bytes>>>(
        x, Tw1, Tb1, Tw2, Tb2, Ew1, Eb1, Ew2, Eb2);
    score_kernel<<<Bsz / 8, 256>>>((float*)d_out);
}

// round 3
// speedup vs baseline: 1.0028x; 1.0028x over previous
#include <cuda_runtime.h>
#include <math.h>

#define Bsz 65536
#define Dd  256
#define Hh  256
#define Kk  11
#define TM  64
#define PAD 257
#define KT  32

// Scratch (no cudaMalloc allowed): encoder outputs
__device__ float g_z [(size_t)Bsz * Hh];            // z  = enc(x)        [B,H]
__device__ float g_zt[(size_t)Kk * Bsz * Hh];       // zt = enc(tx_k)     [K,B,H]

// ---------- packed f32x2 helpers (sm_100+: fma.rn.f32x2) ----------
__device__ __forceinline__ unsigned long long pack2(float a, float b) {
    unsigned long long r;
    asm("mov.b64 %0, {%1, %2};" : "=l"(r) : "f"(a), "f"(b));
    return r;
}
__device__ __forceinline__ unsigned long long fma2(unsigned long long a,
                                                   unsigned long long b,
                                                   unsigned long long c) {
    unsigned long long d;
    asm("fma.rn.f32x2 %0, %1, %2, %3;" : "=l"(d) : "l"(a), "l"(b), "l"(c));
    return d;
}
__device__ __forceinline__ void unpack2(unsigned long long v, float& lo, float& hi) {
    asm("mov.b64 {%0, %1}, %2;" : "=f"(lo), "=f"(hi) : "l"(v));
}

__device__ __forceinline__ float gelu_exact(float v) {
    return 0.5f * v * (1.0f + erff(v * 0.70710678118654752440f));
}

// One dense layer: sout[r][c] = act( sum_kk sin_[r][kk] * W[kk][c] + b[c] )
// sin_/sout: SMEM tiles [TM][PAD]; W: global [256][256] row-major (reduction-major);
// ws: SMEM staging [KT][256].
__device__ __forceinline__ void mlp_layer(
    const float* __restrict__ gW, const float* __restrict__ gb,
    const float* sin_, float* sout, float* ws, bool do_gelu)
{
    const int tid = threadIdx.x;
    const int tx  = tid & 15;   // 16 col-groups
    const int ty  = tid >> 4;   // 16 row-groups

    unsigned long long acc[4][8];
#pragma unroll
    for (int i = 0; i < 4; i++)
#pragma unroll
        for (int j = 0; j < 8; j++) acc[i][j] = 0ull;

    for (int kt = 0; kt < Dd; kt += KT) {
        __syncthreads();  // ws reuse guard (also orders producer writes of sin_)
        const float4* src = (const float4*)(gW + (size_t)kt * Hh);
        float4* dst = (float4*)ws;
#pragma unroll
        for (int i = 0; i < 8; i++) dst[tid + i * 256] = src[tid + i * 256];
        __syncthreads();

#pragma unroll
        for (int kk = 0; kk < KT; kk++) {
            unsigned long long a2[4];
#pragma unroll
            for (int i = 0; i < 4; i++) {
                float a = sin_[(ty + 16 * i) * PAD + kt + kk];
                a2[i] = pack2(a, a);
            }
#pragma unroll
            for (int j = 0; j < 8; j++) {
                unsigned long long w2 =
                    *(const unsigned long long*)(ws + kk * Hh + 2 * tx + 32 * j);
#pragma unroll
                for (int i = 0; i < 4; i++) acc[i][j] = fma2(a2[i], w2, acc[i][j]);
            }
        }
    }
    __syncthreads();

#pragma unroll
    for (int j = 0; j < 8; j++) {
        int c = 2 * tx + 32 * j;
        float b0 = __ldg(gb + c), b1 = __ldg(gb + c + 1);
#pragma unroll
        for (int i = 0; i < 4; i++) {
            float lo, hi;
            unpack2(acc[i][j], lo, hi);
            lo += b0; hi += b1;
            if (do_gelu) { lo = gelu_exact(lo); hi = gelu_exact(hi); }
            int r = ty + 16 * i;
            sout[r * PAD + c]     = lo;
            sout[r * PAD + c + 1] = hi;
        }
    }
}

// FOUR=true : zt_k = enc( gelu(x@Tw1_k+b1)@Tw2_k+b2 )   -> g_zt[k]
// FOUR=false: z    = enc( x )                            -> g_z
template <bool FOUR>
__global__ void __launch_bounds__(256, 1) chain_kernel(
    const float* __restrict__ x,
    const float* __restrict__ Tw1, const float* __restrict__ Tb1,
    const float* __restrict__ Tw2, const float* __restrict__ Tb2,
    const float* __restrict__ Ew1, const float* __restrict__ Eb1,
    const float* __restrict__ Ew2, const float* __restrict__ Eb2)
{
    extern __shared__ float smem[];
    float* bufA = smem;
    float* bufB = smem + TM * PAD;
    float* ws   = smem + 2 * TM * PAD;

    const int    k    = FOUR ? blockIdx.y : 0;
    const size_t row0 = (size_t)blockIdx.x * TM;

    // Load 64x256 input tile (coalesced float4) into bufA
    const float4* gx = (const float4*)(x + row0 * Dd);
    for (int i = threadIdx.x; i < TM * (Dd / 4); i += 256) {
        int r = i >> 6, c4 = i & 63;
        float4 v = gx[(size_t)r * 64 + c4];
        float* d = &bufA[r * PAD + c4 * 4];
        d[0] = v.x; d[1] = v.y; d[2] = v.z; d[3] = v.w;
    }

    if constexpr (FOUR) {
        mlp_layer(Tw1 + (size_t)k * Dd * Hh, Tb1 + k * Hh, bufA, bufB, ws, true);
        mlp_layer(Tw2 + (size_t)k * Hh * Dd, Tb2 + k * Dd, bufB, bufA, ws, false);
        mlp_layer(Ew1, Eb1, bufA, bufB, ws, true);
        mlp_layer(Ew2, Eb2, bufB, bufA, ws, false);
    } else {
        mlp_layer(Ew1, Eb1, bufA, bufB, ws, true);
        mlp_layer(Ew2, Eb2, bufB, bufA, ws, false);
    }
    __syncthreads();

    float* gout = FOUR ? (g_zt + ((size_t)k * Bsz + row0) * Hh)
                       : (g_z + row0 * Hh);
    for (int i = threadIdx.x; i < TM * Hh; i += 256) {
        int r = i >> 8, c = i & 255;
        gout[(size_t)r * Hh + c] = bufA[r * PAD + c];
    }
}

// Pairwise cosine-sim scoring: 1 warp per sample.
__global__ void __launch_bounds__(256) score_kernel(float* __restrict__ out)
{
    const int warp = threadIdx.x >> 5;
    const int lane = threadIdx.x & 31;
    const size_t b = (size_t)blockIdx.x * 8 + warp;

    // vec 0 = z, vec 1+k = zt_k; lane holds elements [lane*8, lane*8+8)
    float v[12][8];
    {
        const float4* p = (const float4*)(g_z + b * Hh) + lane * 2;
        float4 u0 = p[0], u1 = p[1];
        v[0][0]=u0.x; v[0][1]=u0.y; v[0][2]=u0.z; v[0][3]=u0.w;
        v[0][4]=u1.x; v[0][5]=u1.y; v[0][6]=u1.z; v[0][7]=u1.w;
    }
#pragma unroll
    for (int k = 0; k < Kk; k++) {
        const float4* p = (const float4*)(g_zt + ((size_t)k * Bsz + b) * Hh) + lane * 2;
        float4 u0 = p[0], u1 = p[1];
        v[1+k][0]=u0.x; v[1+k][1]=u0.y; v[1+k][2]=u0.z; v[1+k][3]=u0.w;
        v[1+k][4]=u1.x; v[1+k][5]=u1.y; v[1+k][6]=u1.z; v[1+k][7]=u1.w;
    }

    __shared__ float dots[8][80];  // 78 pair-dots per warp
    int idx = 0;
#pragma unroll
    for (int p = 0; p < 12; p++) {
#pragma unroll
        for (int q = p; q < 12; q++) {
            float s = 0.f;
#pragma unroll
            for (int e = 0; e < 8; e++) s += v[p][e] * v[q][e];
#pragma unroll
            for (int off = 16; off; off >>= 1)
                s += __shfl_xor_sync(0xffffffffu, s, off);
            if (lane == 0) dots[warp][idx] = s;
            idx++;
        }
    }
    __syncwarp();

    auto pidx = [](int p, int q) {
        if (p > q) { int t = p; p = q; q = t; }
        return p * 12 - p * (p + 1) / 2 + q;
    };

    float score = 0.f;
    if (lane < Kk) {
        const float* d = dots[warp];
        int kv = 1 + lane;
        float nz = sqrtf(d[pidx(0, 0)]);
        float nk = sqrtf(d[pidx(kv, kv)]);
        float simz = expf(d[pidx(0, kv)] / fmaxf(nz * nk, 1e-8f));
        float neg = 0.f;
        for (int l = 0; l < Kk; l++) {
            if (l == lane) continue;
            int lv = 1 + l;
            float nl = sqrtf(d[pidx(lv, lv)]);
            neg += expf(d[pidx(lv, kv)] / fmaxf(nl * nk, 1e-8f));
        }
        score = logf(simz / (simz + neg));
    }
#pragma unroll
    for (int off = 16; off; off >>= 1)
        score += __shfl_xor_sync(0xffffffffu, score, off);
    if (lane == 0) out[b] = -score;
}

extern "C" void kernel_launch(void* const* d_in, const int* in_sizes, int n_in,
                              void* d_out, int out_size)
{
    const float* x   = (const float*)d_in[0];
    const float* Tw1 = (const float*)d_in[1];
    const float* Tb1 = (const float*)d_in[2];
    const float* Tw2 = (const float*)d_in[3];
    const float* Tb2 = (const float*)d_in[4];
    const float* Ew1 = (const float*)d_in[5];
    const float* Eb1 = (const float*)d_in[6];
    const float* Ew2 = (const float*)d_in[7];
    const float* Eb2 = (const float*)d_in[8];

    const int smem_bytes = (2 * TM * PAD + KT * Hh) * sizeof(float);  // ~160.5 KB
    cudaFuncSetAttribute(chain_kernel<true>,
                         cudaFuncAttributeMaxDynamicSharedMemorySize, smem_bytes);
    cudaFuncSetAttribute(chain_kernel<false>,
                         cudaFuncAttributeMaxDynamicSharedMemorySize, smem_bytes);

    chain_kernel<false><<<Bsz / TM, 256, smem_bytes>>>(
        x, nullptr, nullptr, nullptr, nullptr, Ew1, Eb1, Ew2, Eb2);
    chain_kernel<true><<<dim3(Bsz / TM, Kk), 256, smem_bytes>>>(
        x, Tw1, Tb1, Tw2, Tb2, Ew1, Eb1, Ew2, Eb2);
    score_kernel<<<Bsz / 8, 256>>>((float*)d_out);
}

// round 16
// speedup vs baseline: 3.4820x; 3.4722x over previous
#include <cuda_runtime.h>
#include <stdint.h>
#include <math.h>

#define Bsz 65536
#define Kk  11

// ---------------- device scratch (no cudaMalloc allowed) ----------------
__device__ float    g_z [(size_t)Bsz * 256];
__device__ float    g_zt[(size_t)Kk * Bsz * 256];
__device__ float    g_Wf[(size_t)Kk * 256 * 256];     // Tw2_k @ Ew1
__device__ float    g_cf[Kk * 256];                   // Tb2_k @ Ew1 + Eb1
__device__ uint32_t g_wimg[(size_t)24 * 65536];       // 24 weight images x 256KB

// ---------------- helpers ----------------
__device__ __forceinline__ uint32_t smem_u32(const void* p) {
    uint32_t a;
    asm("{ .reg .u64 t; cvta.to.shared.u64 t, %1; cvt.u32.u64 %0, t; }" : "=r"(a) : "l"(p));
    return a;
}
#define STS32(addr,val) \
    asm volatile("st.shared.b32 [%0], %1;" :: "r"(addr), "r"(val) : "memory")
#define STS64(addr,val) \
    asm volatile("st.shared.b64 [%0], %1;" :: "r"(addr), "l"(val) : "memory")
#define CP16(dst,src) \
    asm volatile("cp.async.cg.shared.global [%0], [%1], 16;" :: "r"(dst), "l"(src) : "memory")
#define CP_COMMIT() asm volatile("cp.async.commit_group;" ::: "memory")
#define CP_WAIT1()  asm volatile("cp.async.wait_group 1;" ::: "memory")

__device__ __forceinline__ void ldsm4(uint32_t* r, uint32_t a) {
    asm volatile("ldmatrix.sync.aligned.m8n8.x4.shared.b16 {%0,%1,%2,%3}, [%4];"
        : "=r"(r[0]), "=r"(r[1]), "=r"(r[2]), "=r"(r[3]) : "r"(a));
}
__device__ __forceinline__ void mma_bf16(float* d, const uint32_t* a, const uint32_t* b) {
    asm volatile("mma.sync.aligned.m16n8k16.row.col.f32.bf16.bf16.f32 "
        "{%0,%1,%2,%3}, {%4,%5,%6,%7}, {%8,%9}, {%0,%1,%2,%3};"
        : "+f"(d[0]), "+f"(d[1]), "+f"(d[2]), "+f"(d[3])
        : "r"(a[0]), "r"(a[1]), "r"(a[2]), "r"(a[3]), "r"(b[0]), "r"(b[1]));
}
__device__ __forceinline__ uint32_t pack_bf16x2(float lo, float hi) {
    uint32_t r;  // hi -> upper 16 bits, lo -> lower 16 bits
    asm("cvt.rn.bf16x2.f32 %0, %1, %2;" : "=r"(r) : "f"(hi), "f"(lo));
    return r;
}
__device__ __forceinline__ float lo16f(uint32_t p) { return __uint_as_float(p << 16); }
__device__ __forceinline__ float hi16f(uint32_t p) { return __uint_as_float(p & 0xffff0000u); }
__device__ __forceinline__ unsigned long long pk64(uint32_t a, uint32_t b) {
    unsigned long long r;
    asm("mov.b64 %0, {%1,%2};" : "=l"(r) : "r"(a), "r"(b));
    return r;
}
__device__ __forceinline__ float gelu(float v) {
    return 0.5f * v * (1.0f + erff(v * 0.70710678118654752440f));
}

// ---------------- SMEM layout ----------------
// A: 8 k-slices x 16KB. Slice s holds k in [32s,32s+32): atom (r>>3) of 1KB,
//    row (r&7) is 128B: [hi bf16 k32 | lo bf16 k32], columns XOR-swizzled with (r&7)<<4.
// B: 2 buffers x 32KB, same scheme with n rows (32 atoms/slice).
#define SM_A     0
#define SM_B     131072
#define SM_TOTAL 196608

// One layer: D[128x256] = A[128x256] @ W^T, 3-product bf16 split, warp tile m64 x n64.
// mode 0: +bias, gelu, re-split into A (in place). mode 1: +bias, fp32 -> gout (staged).
__device__ __noinline__ void do_layer(
    const char* __restrict__ img, const float* __restrict__ bias,
    int mode, float* __restrict__ gout, char* sm, uint32_t sb)
{
    const int tid = threadIdx.x, lane = tid & 31, w = tid >> 5;
    const int mbase = (w & 1) * 64, nbase = (w >> 1) * 64;

    float acc[4][8][4];
#pragma unroll
    for (int i = 0; i < 4; i++)
#pragma unroll
        for (int j = 0; j < 8; j++)
#pragma unroll
            for (int q = 0; q < 4; q++) acc[i][j][q] = 0.f;

    // ldmatrix lane geometry
    const int am = mbase + (lane & 7) + ((lane >> 3) & 1) * 8;  // + mt*16
    const int ak = (lane >> 4) << 3;                             // + 16*kk
    const int bn = nbase + (lane & 7) + ((lane >> 4) << 3);      // + bt*16
    const int bk = ((lane >> 3) & 1) << 3;

    uint32_t aBase[4], bBase[4];
#pragma unroll
    for (int t = 0; t < 4; t++) {
        const int m = am + t * 16, n = bn + t * 16;
        aBase[t] = ((uint32_t)(m >> 3) << 10) + (uint32_t)(m & 7) * 128u;
        bBase[t] = ((uint32_t)(n >> 3) << 10) + (uint32_t)(n & 7) * 128u;
    }
    const uint32_t amask = (uint32_t)(am & 7) << 4;
    const uint32_t bmask = (uint32_t)(bn & 7) << 4;

    // slice staging (32KB contiguous per slice)
    const uint32_t bufs = sb + SM_B;
#define CP_SLICE(s, buf) do { \
        const char* _src = img + (size_t)(s) * 32768 + tid * 16; \
        uint32_t _d = bufs + (uint32_t)(buf) * 32768u + (uint32_t)tid * 16u; \
        _Pragma("unroll") \
        for (int _i = 0; _i < 8; _i++) CP16(_d + _i * 4096u, _src + _i * 4096); \
    } while (0)

    CP_SLICE(0, 0); CP_COMMIT();
    CP_SLICE(1, 1); CP_COMMIT();

#pragma unroll 1
    for (int ks = 0; ks < 8; ks++) {
        CP_WAIT1();
        __syncthreads();
        const uint32_t Ab = sb + SM_A + (uint32_t)ks * 16384u;
        const uint32_t Bb = bufs + (uint32_t)(ks & 1) * 32768u;
#pragma unroll
        for (int kk = 0; kk < 2; kk++) {
            const uint32_t ac = (uint32_t)((kk * 16 + ak) * 2);
            const uint32_t bc = (uint32_t)((kk * 16 + bk) * 2);
            uint32_t Ah[4][4], Bx[4][4], Al[4][4];
#pragma unroll
            for (int t = 0; t < 4; t++) ldsm4(Ah[t], Ab + aBase[t] + (ac ^ amask));
#pragma unroll
            for (int t = 0; t < 4; t++) ldsm4(Bx[t], Bb + bBase[t] + (bc ^ bmask));
#pragma unroll
            for (int mt = 0; mt < 4; mt++)
#pragma unroll
                for (int nt = 0; nt < 8; nt++)
                    mma_bf16(acc[mt][nt], Ah[mt], &Bx[nt >> 1][(nt & 1) * 2]);
#pragma unroll
            for (int t = 0; t < 4; t++) ldsm4(Al[t], Ab + aBase[t] + ((ac + 64u) ^ amask));
#pragma unroll
            for (int mt = 0; mt < 4; mt++)
#pragma unroll
                for (int nt = 0; nt < 8; nt++)
                    mma_bf16(acc[mt][nt], Al[mt], &Bx[nt >> 1][(nt & 1) * 2]);
#pragma unroll
            for (int t = 0; t < 4; t++) ldsm4(Bx[t], Bb + bBase[t] + ((bc + 64u) ^ bmask));
#pragma unroll
            for (int mt = 0; mt < 4; mt++)
#pragma unroll
                for (int nt = 0; nt < 8; nt++)
                    mma_bf16(acc[mt][nt], Ah[mt], &Bx[nt >> 1][(nt & 1) * 2]);
        }
        __syncthreads();
        if (ks < 6) CP_SLICE(ks + 2, ks & 1);
        CP_COMMIT();
    }
#undef CP_SLICE

    // epilogue. D frag: d0,d1 at row lane/4, cols (lane&3)*2 +{0,1}; d2,d3 at row+8.
    const int erow = lane >> 2, ecol = (lane & 3) * 2;
    if (mode == 0) {
#pragma unroll
        for (int mt = 0; mt < 4; mt++)
#pragma unroll
            for (int nt = 0; nt < 8; nt++) {
                const int n0 = nbase + nt * 8 + ecol;
                const float b0 = __ldg(bias + n0), b1 = __ldg(bias + n0 + 1);
#pragma unroll
                for (int p = 0; p < 2; p++) {
                    const int r = mbase + mt * 16 + erow + p * 8;
                    float v0 = gelu(acc[mt][nt][p * 2] + b0);
                    float v1 = gelu(acc[mt][nt][p * 2 + 1] + b1);
                    uint32_t hi = pack_bf16x2(v0, v1);
                    uint32_t lo = pack_bf16x2(v0 - lo16f(hi), v1 - hi16f(hi));
                    uint32_t base = sb + SM_A + (uint32_t)(n0 >> 5) * 16384u
                                  + (uint32_t)(r >> 3) * 1024u + (uint32_t)(r & 7) * 128u;
                    uint32_t msk = (uint32_t)(r & 7) << 4;
                    uint32_t c = (uint32_t)(n0 & 31) * 2u;
                    STS32(base + (c ^ msk), hi);
                    STS32(base + ((c + 64u) ^ msk), lo);
                }
            }
        // next layer's first __syncthreads orders these stores vs. ldmatrix reads
    } else {
        // stage fp32 [128][256] into the A region, then coalesced float4 writes
#pragma unroll
        for (int mt = 0; mt < 4; mt++)
#pragma unroll
            for (int nt = 0; nt < 8; nt++) {
                const int n0 = nbase + nt * 8 + ecol;
                const float b0 = __ldg(bias + n0), b1 = __ldg(bias + n0 + 1);
#pragma unroll
                for (int p = 0; p < 2; p++) {
                    const int r = mbase + mt * 16 + erow + p * 8;
                    float2 v;
                    v.x = acc[mt][nt][p * 2] + b0;
                    v.y = acc[mt][nt][p * 2 + 1] + b1;
                    *(float2*)(sm + (size_t)r * 1024 + (size_t)n0 * 4) = v;
                }
            }
        __syncthreads();
#pragma unroll
        for (int i = 0; i < 32; i++) {
            const int idx = tid + 256 * i;
            ((float4*)gout)[idx] = ((const float4*)sm)[idx];
        }
    }
}

__device__ __forceinline__ const char* imgp(int i) {
    return (const char*)g_wimg + (size_t)i * 262144;
}

// y=0: z = enc(x).  y=k+1: zt_k = gelu(x@Tw1+Tb1) -> gelu(.@Wf+cf) -> .@Ew2+Eb2
__global__ void __launch_bounds__(256, 1) chain_kernel(
    const float* __restrict__ x,
    const float* __restrict__ Tb1,
    const float* __restrict__ Eb1,
    const float* __restrict__ Eb2)
{
    extern __shared__ char sm[];
    const uint32_t sb = smem_u32(sm);
    const int tid = threadIdx.x;

    // A = bf16 hi/lo split of the 128x256 x tile
    const float4* xt = (const float4*)(x + (size_t)blockIdx.x * 128 * 256);
#pragma unroll
    for (int i = 0; i < 32; i++) {
        const int idx = tid + 256 * i;
        const int r = idx >> 6, k = (idx & 63) * 4;
        float4 v = xt[idx];
        uint32_t h0 = pack_bf16x2(v.x, v.y), h1 = pack_bf16x2(v.z, v.w);
        uint32_t l0 = pack_bf16x2(v.x - lo16f(h0), v.y - hi16f(h0));
        uint32_t l1 = pack_bf16x2(v.z - lo16f(h1), v.w - hi16f(h1));
        uint32_t base = sb + SM_A + (uint32_t)(k >> 5) * 16384u
                      + (uint32_t)(r >> 3) * 1024u + (uint32_t)(r & 7) * 128u;
        uint32_t msk = (uint32_t)(r & 7) << 4;
        uint32_t c = (uint32_t)(k & 31) * 2u;
        STS64(base + (c ^ msk), pk64(h0, h1));
        STS64(base + ((c + 64u) ^ msk), pk64(l0, l1));
    }

    const int y = blockIdx.y;
    const size_t row0 = (size_t)blockIdx.x * 128;
    if (y == 0) {
        do_layer(imgp(22), Eb1, 0, nullptr, sm, sb);
        do_layer(imgp(23), Eb2, 1, g_z + row0 * 256, sm, sb);
    } else {
        const int k = y - 1;
        do_layer(imgp(k),      Tb1 + k * 256,  0, nullptr, sm, sb);
        do_layer(imgp(11 + k), g_cf + k * 256, 0, nullptr, sm, sb);
        do_layer(imgp(23),     Eb2,            1, g_zt + ((size_t)k * Bsz + row0) * 256, sm, sb);
    }
}

// ---------------- prep kernels ----------------
__global__ void __launch_bounds__(256) prep_wf(const float* __restrict__ Tw2,
                                               const float* __restrict__ Ew1)
{
    __shared__ float s[32][256];
    const int k = blockIdx.x, i0 = blockIdx.y * 32, tid = threadIdx.x;
    for (int idx = tid; idx < 32 * 256; idx += 256)
        s[idx >> 8][idx & 255] = Tw2[((size_t)k * 256 + i0 + (idx >> 8)) * 256 + (idx & 255)];
    __syncthreads();
    float acc[32];
#pragma unroll
    for (int i = 0; i < 32; i++) acc[i] = 0.f;
    for (int j = 0; j < 256; j++) {
        const float wv = __ldg(Ew1 + j * 256 + tid);
#pragma unroll
        for (int i = 0; i < 32; i++) acc[i] += s[i][j] * wv;
    }
    for (int i = 0; i < 32; i++)
        g_Wf[((size_t)k * 256 + i0 + i) * 256 + tid] = acc[i];
}

__global__ void prep_cf(const float* __restrict__ Tb2, const float* __restrict__ Ew1,
                        const float* __restrict__ Eb1)
{
    const int k = blockIdx.x, t = threadIdx.x;
    float a = Eb1[t];
    for (int j = 0; j < 256; j++) a += Tb2[k * 256 + j] * __ldg(Ew1 + j * 256 + t);
    g_cf[k * 256 + t] = a;
}

// fp32 W[kred][n] -> image: 8 k-slices x 32KB; atom (n>>3) 1KB; row (n&7) 128B
// = [hi k32 | lo k32] bf16, columns XOR-swizzled by (n&7)<<4.
__global__ void __launch_bounds__(256) prep_img(const float* __restrict__ Tw1,
                                                const float* __restrict__ Ew1,
                                                const float* __restrict__ Ew2)
{
    const int idx = blockIdx.x;
    const float* src;
    if (idx < 11)       src = Tw1 + (size_t)idx * 65536;
    else if (idx < 22)  src = g_Wf + (size_t)(idx - 11) * 65536;
    else if (idx == 22) src = Ew1;
    else                src = Ew2;
    char* img = (char*)g_wimg + (size_t)idx * 262144;

    const int lane = threadIdx.x & 31, wid = threadIdx.x >> 5;
    const int n = blockIdx.y * 32 + lane;
    for (int it = 0; it < 4; it++) {
        const int kc = (wid * 4 + it) * 8;
        float v[8];
#pragma unroll
        for (int i = 0; i < 8; i++) v[i] = __ldg(src + (size_t)(kc + i) * 256 + n);
        uint32_t hi[4], lo[4];
#pragma unroll
        for (int j = 0; j < 4; j++) {
            uint32_t p = pack_bf16x2(v[2 * j], v[2 * j + 1]);
            hi[j] = p;
            lo[j] = pack_bf16x2(v[2 * j] - lo16f(p), v[2 * j + 1] - hi16f(p));
        }
        uint32_t base = (uint32_t)((kc >> 5) * 32768 + (n >> 3) * 1024 + (n & 7) * 128);
        uint32_t msk = (uint32_t)(n & 7) << 4;
        uint32_t c = (uint32_t)(kc & 31) * 2u;
        *(uint4*)(img + base + (c ^ msk))        = make_uint4(hi[0], hi[1], hi[2], hi[3]);
        *(uint4*)(img + base + ((c + 64u) ^ msk)) = make_uint4(lo[0], lo[1], lo[2], lo[3]);
    }
}

// ---------------- scoring (1 warp per sample) ----------------
__global__ void __launch_bounds__(256) score_kernel(float* __restrict__ out)
{
    const int warp = threadIdx.x >> 5;
    const int lane = threadIdx.x & 31;
    const size_t b = (size_t)blockIdx.x * 8 + warp;

    float v[12][8];
    {
        const float4* p = (const float4*)(g_z + b * 256) + lane * 2;
        float4 u0 = p[0], u1 = p[1];
        v[0][0]=u0.x; v[0][1]=u0.y; v[0][2]=u0.z; v[0][3]=u0.w;
        v[0][4]=u1.x; v[0][5]=u1.y; v[0][6]=u1.z; v[0][7]=u1.w;
    }
#pragma unroll
    for (int k = 0; k < Kk; k++) {
        const float4* p = (const float4*)(g_zt + ((size_t)k * Bsz + b) * 256) + lane * 2;
        float4 u0 = p[0], u1 = p[1];
        v[1+k][0]=u0.x; v[1+k][1]=u0.y; v[1+k][2]=u0.z; v[1+k][3]=u0.w;
        v[1+k][4]=u1.x; v[1+k][5]=u1.y; v[1+k][6]=u1.z; v[1+k][7]=u1.w;
    }

    __shared__ float dots[8][80];
    int idx = 0;
#pragma unroll
    for (int p = 0; p < 12; p++) {
#pragma unroll
        for (int q = p; q < 12; q++) {
            float s = 0.f;
#pragma unroll
            for (int e = 0; e < 8; e++) s += v[p][e] * v[q][e];
#pragma unroll
            for (int off = 16; off; off >>= 1)
                s += __shfl_xor_sync(0xffffffffu, s, off);
            if (lane == 0) dots[warp][idx] = s;
            idx++;
        }
    }
    __syncwarp();

    auto pidx = [](int p, int q) {
        if (p > q) { int t = p; p = q; q = t; }
        return p * 12 - p * (p + 1) / 2 + q;
    };

    float score = 0.f;
    if (lane < Kk) {
        const float* d = dots[warp];
        const int kv = 1 + lane;
        float nz = sqrtf(d[pidx(0, 0)]);
        float nk = sqrtf(d[pidx(kv, kv)]);
        float simz = expf(d[pidx(0, kv)] / fmaxf(nz * nk, 1e-8f));
        float neg = 0.f;
        for (int l = 0; l < Kk; l++) {
            if (l == lane) continue;
            const int lv = 1 + l;
            float nl = sqrtf(d[pidx(lv, lv)]);
            neg += expf(d[pidx(lv, kv)] / fmaxf(nl * nk, 1e-8f));
        }
        score = logf(simz / (simz + neg));
    }
#pragma unroll
    for (int off = 16; off; off >>= 1)
        score += __shfl_xor_sync(0xffffffffu, score, off);
    if (lane == 0) out[b] = -score;
}

extern "C" void kernel_launch(void* const* d_in, const int* in_sizes, int n_in,
                              void* d_out, int out_size)
{
    const float* x   = (const float*)d_in[0];
    const float* Tw1 = (const float*)d_in[1];
    const float* Tb1 = (const float*)d_in[2];
    const float* Tw2 = (const float*)d_in[3];
    const float* Tb2 = (const float*)d_in[4];
    const float* Ew1 = (const float*)d_in[5];
    const float* Eb1 = (const float*)d_in[6];
    const float* Ew2 = (const float*)d_in[7];
    const float* Eb2 = (const float*)d_in[8];

    prep_wf<<<dim3(11, 8), 256>>>(Tw2, Ew1);
    prep_cf<<<11, 256>>>(Tb2, Ew1, Eb1);
    prep_img<<<dim3(24, 8), 256>>>(Tw1, Ew1, Ew2);

    cudaFuncSetAttribute(chain_kernel,
                         cudaFuncAttributeMaxDynamicSharedMemorySize, SM_TOTAL);
    chain_kernel<<<dim3(512, 12), 256, SM_TOTAL>>>(x, Tb1, Eb1, Eb2);

    score_kernel<<<Bsz / 8, 256>>>((float*)d_out);
}

// round 17
// speedup vs baseline: 3.4825x; 1.0001x over previous
#include <cuda_runtime.h>
#include <stdint.h>
#include <math.h>

#define Bsz 65536
#define Kk  11

// ---------------- device scratch (no cudaMalloc allowed) ----------------
__device__ float    g_z [(size_t)Bsz * 256];
__device__ float    g_zt[(size_t)Kk * Bsz * 256];
__device__ float    g_Wf[(size_t)Kk * 256 * 256];     // Tw2_k @ Ew1
__device__ float    g_cf[Kk * 256];                   // Tb2_k @ Ew1 + Eb1
__device__ uint32_t g_wimg[(size_t)24 * 65536];       // 24 weight images x 256KB

// ---------------- helpers ----------------
__device__ __forceinline__ uint32_t smem_u32(const void* p) {
    uint32_t a;
    asm("{ .reg .u64 t; cvta.to.shared.u64 t, %1; cvt.u32.u64 %0, t; }" : "=r"(a) : "l"(p));
    return a;
}
#define STS32(addr,val) \
    asm volatile("st.shared.b32 [%0], %1;" :: "r"(addr), "r"(val) : "memory")
#define STS64(addr,val) \
    asm volatile("st.shared.b64 [%0], %1;" :: "r"(addr), "l"(val) : "memory")
#define CP16(dst,src) \
    asm volatile("cp.async.cg.shared.global [%0], [%1], 16;" :: "r"(dst), "l"(src) : "memory")
#define CP_COMMIT() asm volatile("cp.async.commit_group;" ::: "memory")
#define CP_WAIT1()  asm volatile("cp.async.wait_group 1;" ::: "memory")

__device__ __forceinline__ void ldsm4(uint32_t* r, uint32_t a) {
    asm volatile("ldmatrix.sync.aligned.m8n8.x4.shared.b16 {%0,%1,%2,%3}, [%4];"
        : "=r"(r[0]), "=r"(r[1]), "=r"(r[2]), "=r"(r[3]) : "r"(a));
}
__device__ __forceinline__ void mma_bf16(float* d, const uint32_t* a, const uint32_t* b) {
    asm volatile("mma.sync.aligned.m16n8k16.row.col.f32.bf16.bf16.f32 "
        "{%0,%1,%2,%3}, {%4,%5,%6,%7}, {%8,%9}, {%0,%1,%2,%3};"
        : "+f"(d[0]), "+f"(d[1]), "+f"(d[2]), "+f"(d[3])
        : "r"(a[0]), "r"(a[1]), "r"(a[2]), "r"(a[3]), "r"(b[0]), "r"(b[1]));
}
__device__ __forceinline__ uint32_t pack_bf16x2(float lo, float hi) {
    uint32_t r;  // hi -> upper 16 bits, lo -> lower 16 bits
    asm("cvt.rn.bf16x2.f32 %0, %1, %2;" : "=r"(r) : "f"(hi), "f"(lo));
    return r;
}
__device__ __forceinline__ float lo16f(uint32_t p) { return __uint_as_float(p << 16); }
__device__ __forceinline__ float hi16f(uint32_t p) { return __uint_as_float(p & 0xffff0000u); }
__device__ __forceinline__ unsigned long long pk64(uint32_t a, uint32_t b) {
    unsigned long long r;
    asm("mov.b64 %0, {%1,%2};" : "=l"(r) : "r"(a), "r"(b));
    return r;
}
__device__ __forceinline__ float gelu(float v) {
    return 0.5f * v * (1.0f + erff(v * 0.70710678118654752440f));
}

// ---------------- SMEM layout ----------------
// A: 8 k-slices x 16KB. Slice s holds k in [32s,32s+32): atom (r>>3) of 1KB,
//    row (r&7) is 128B: [hi bf16 k32 | lo bf16 k32], columns XOR-swizzled with (r&7)<<4.
// B: 2 buffers x 32KB, same scheme with n rows (32 atoms/slice).
#define SM_A     0
#define SM_B     131072
#define SM_TOTAL 196608

// One layer: D[128x256] = A[128x256] @ W^T, 3-product bf16 split, warp tile m64 x n64.
// mode 0: +bias, gelu, re-split into A (in place). mode 1: +bias, fp32 -> gout (staged).
__device__ __noinline__ void do_layer(
    const char* __restrict__ img, const float* __restrict__ bias,
    int mode, float* __restrict__ gout, char* sm, uint32_t sb)
{
    const int tid = threadIdx.x, lane = tid & 31, w = tid >> 5;
    const int mbase = (w & 1) * 64, nbase = (w >> 1) * 64;

    float acc[4][8][4];
#pragma unroll
    for (int i = 0; i < 4; i++)
#pragma unroll
        for (int j = 0; j < 8; j++)
#pragma unroll
            for (int q = 0; q < 4; q++) acc[i][j][q] = 0.f;

    // ldmatrix lane geometry
    const int am = mbase + (lane & 7) + ((lane >> 3) & 1) * 8;  // + mt*16
    const int ak = (lane >> 4) << 3;                             // + 16*kk
    const int bn = nbase + (lane & 7) + ((lane >> 4) << 3);      // + bt*16
    const int bk = ((lane >> 3) & 1) << 3;

    uint32_t aBase[4], bBase[4];
#pragma unroll
    for (int t = 0; t < 4; t++) {
        const int m = am + t * 16, n = bn + t * 16;
        aBase[t] = ((uint32_t)(m >> 3) << 10) + (uint32_t)(m & 7) * 128u;
        bBase[t] = ((uint32_t)(n >> 3) << 10) + (uint32_t)(n & 7) * 128u;
    }
    const uint32_t amask = (uint32_t)(am & 7) << 4;
    const uint32_t bmask = (uint32_t)(bn & 7) << 4;

    // slice staging (32KB contiguous per slice)
    const uint32_t bufs = sb + SM_B;
#define CP_SLICE(s, buf) do { \
        const char* _src = img + (size_t)(s) * 32768 + tid * 16; \
        uint32_t _d = bufs + (uint32_t)(buf) * 32768u + (uint32_t)tid * 16u; \
        _Pragma("unroll") \
        for (int _i = 0; _i < 8; _i++) CP16(_d + _i * 4096u, _src + _i * 4096); \
    } while (0)

    CP_SLICE(0, 0); CP_COMMIT();
    CP_SLICE(1, 1); CP_COMMIT();

#pragma unroll 1
    for (int ks = 0; ks < 8; ks++) {
        CP_WAIT1();
        __syncthreads();
        const uint32_t Ab = sb + SM_A + (uint32_t)ks * 16384u;
        const uint32_t Bb = bufs + (uint32_t)(ks & 1) * 32768u;
#pragma unroll
        for (int kk = 0; kk < 2; kk++) {
            const uint32_t ac = (uint32_t)((kk * 16 + ak) * 2);
            const uint32_t bc = (uint32_t)((kk * 16 + bk) * 2);
            uint32_t Ah[4][4], Bx[4][4], Al[4][4];
#pragma unroll
            for (int t = 0; t < 4; t++) ldsm4(Ah[t], Ab + aBase[t] + (ac ^ amask));
#pragma unroll
            for (int t = 0; t < 4; t++) ldsm4(Bx[t], Bb + bBase[t] + (bc ^ bmask));
#pragma unroll
            for (int mt = 0; mt < 4; mt++)
#pragma unroll
                for (int nt = 0; nt < 8; nt++)
                    mma_bf16(acc[mt][nt], Ah[mt], &Bx[nt >> 1][(nt & 1) * 2]);
#pragma unroll
            for (int t = 0; t < 4; t++) ldsm4(Al[t], Ab + aBase[t] + ((ac + 64u) ^ amask));
#pragma unroll
            for (int mt = 0; mt < 4; mt++)
#pragma unroll
                for (int nt = 0; nt < 8; nt++)
                    mma_bf16(acc[mt][nt], Al[mt], &Bx[nt >> 1][(nt & 1) * 2]);
#pragma unroll
            for (int t = 0; t < 4; t++) ldsm4(Bx[t], Bb + bBase[t] + ((bc + 64u) ^ bmask));
#pragma unroll
            for (int mt = 0; mt < 4; mt++)
#pragma unroll
                for (int nt = 0; nt < 8; nt++)
                    mma_bf16(acc[mt][nt], Ah[mt], &Bx[nt >> 1][(nt & 1) * 2]);
        }
        __syncthreads();
        if (ks < 6) CP_SLICE(ks + 2, ks & 1);
        CP_COMMIT();
    }
#undef CP_SLICE

    // epilogue. D frag: d0,d1 at row lane/4, cols (lane&3)*2 +{0,1}; d2,d3 at row+8.
    const int erow = lane >> 2, ecol = (lane & 3) * 2;
    if (mode == 0) {
#pragma unroll
        for (int mt = 0; mt < 4; mt++)
#pragma unroll
            for (int nt = 0; nt < 8; nt++) {
                const int n0 = nbase + nt * 8 + ecol;
                const float b0 = __ldg(bias + n0), b1 = __ldg(bias + n0 + 1);
#pragma unroll
                for (int p = 0; p < 2; p++) {
                    const int r = mbase + mt * 16 + erow + p * 8;
                    float v0 = gelu(acc[mt][nt][p * 2] + b0);
                    float v1 = gelu(acc[mt][nt][p * 2 + 1] + b1);
                    uint32_t hi = pack_bf16x2(v0, v1);
                    uint32_t lo = pack_bf16x2(v0 - lo16f(hi), v1 - hi16f(hi));
                    uint32_t base = sb + SM_A + (uint32_t)(n0 >> 5) * 16384u
                                  + (uint32_t)(r >> 3) * 1024u + (uint32_t)(r & 7) * 128u;
                    uint32_t msk = (uint32_t)(r & 7) << 4;
                    uint32_t c = (uint32_t)(n0 & 31) * 2u;
                    STS32(base + (c ^ msk), hi);
                    STS32(base + ((c + 64u) ^ msk), lo);
                }
            }
        // next layer's first __syncthreads orders these stores vs. ldmatrix reads
    } else {
        // stage fp32 [128][256] into the A region, then coalesced float4 writes
#pragma unroll
        for (int mt = 0; mt < 4; mt++)
#pragma unroll
            for (int nt = 0; nt < 8; nt++) {
                const int n0 = nbase + nt * 8 + ecol;
                const float b0 = __ldg(bias + n0), b1 = __ldg(bias + n0 + 1);
#pragma unroll
                for (int p = 0; p < 2; p++) {
                    const int r = mbase + mt * 16 + erow + p * 8;
                    float2 v;
                    v.x = acc[mt][nt][p * 2] + b0;
                    v.y = acc[mt][nt][p * 2 + 1] + b1;
                    *(float2*)(sm + (size_t)r * 1024 + (size_t)n0 * 4) = v;
                }
            }
        __syncthreads();
#pragma unroll
        for (int i = 0; i < 32; i++) {
            const int idx = tid + 256 * i;
            ((float4*)gout)[idx] = ((const float4*)sm)[idx];
        }
    }
}

__device__ __forceinline__ const char* imgp(int i) {
    return (const char*)g_wimg + (size_t)i * 262144;
}

// y=0: z = enc(x).  y=k+1: zt_k = gelu(x@Tw1+Tb1) -> gelu(.@Wf+cf) -> .@Ew2+Eb2
__global__ void __launch_bounds__(256, 1) chain_kernel(
    const float* __restrict__ x,
    const float* __restrict__ Tb1,
    const float* __restrict__ Eb1,
    const float* __restrict__ Eb2)
{
    extern __shared__ char sm[];
    const uint32_t sb = smem_u32(sm);
    const int tid = threadIdx.x;

    // A = bf16 hi/lo split of the 128x256 x tile
    const float4* xt = (const float4*)(x + (size_t)blockIdx.x * 128 * 256);
#pragma unroll
    for (int i = 0; i < 32; i++) {
        const int idx = tid + 256 * i;
        const int r = idx >> 6, k = (idx & 63) * 4;
        float4 v = xt[idx];
        uint32_t h0 = pack_bf16x2(v.x, v.y), h1 = pack_bf16x2(v.z, v.w);
        uint32_t l0 = pack_bf16x2(v.x - lo16f(h0), v.y - hi16f(h0));
        uint32_t l1 = pack_bf16x2(v.z - lo16f(h1), v.w - hi16f(h1));
        uint32_t base = sb + SM_A + (uint32_t)(k >> 5) * 16384u
                      + (uint32_t)(r >> 3) * 1024u + (uint32_t)(r & 7) * 128u;
        uint32_t msk = (uint32_t)(r & 7) << 4;
        uint32_t c = (uint32_t)(k & 31) * 2u;
        STS64(base + (c ^ msk), pk64(h0, h1));
        STS64(base + ((c + 64u) ^ msk), pk64(l0, l1));
    }

    const int y = blockIdx.y;
    const size_t row0 = (size_t)blockIdx.x * 128;
    if (y == 0) {
        do_layer(imgp(22), Eb1, 0, nullptr, sm, sb);
        do_layer(imgp(23), Eb2, 1, g_z + row0 * 256, sm, sb);
    } else {
        const int k = y - 1;
        do_layer(imgp(k),      Tb1 + k * 256,  0, nullptr, sm, sb);
        do_layer(imgp(11 + k), g_cf + k * 256, 0, nullptr, sm, sb);
        do_layer(imgp(23),     Eb2,            1, g_zt + ((size_t)k * Bsz + row0) * 256, sm, sb);
    }
}

// ---------------- prep kernels ----------------
__global__ void __launch_bounds__(256) prep_wf(const float* __restrict__ Tw2,
                                               const float* __restrict__ Ew1)
{
    __shared__ float s[32][256];
    const int k = blockIdx.x, i0 = blockIdx.y * 32, tid = threadIdx.x;
    for (int idx = tid; idx < 32 * 256; idx += 256)
        s[idx >> 8][idx & 255] = Tw2[((size_t)k * 256 + i0 + (idx >> 8)) * 256 + (idx & 255)];
    __syncthreads();
    float acc[32];
#pragma unroll
    for (int i = 0; i < 32; i++) acc[i] = 0.f;
    for (int j = 0; j < 256; j++) {
        const float wv = __ldg(Ew1 + j * 256 + tid);
#pragma unroll
        for (int i = 0; i < 32; i++) acc[i] += s[i][j] * wv;
    }
    for (int i = 0; i < 32; i++)
        g_Wf[((size_t)k * 256 + i0 + i) * 256 + tid] = acc[i];
}

__global__ void prep_cf(const float* __restrict__ Tb2, const float* __restrict__ Ew1,
                        const float* __restrict__ Eb1)
{
    const int k = blockIdx.x, t = threadIdx.x;
    float a = Eb1[t];
    for (int j = 0; j < 256; j++) a += Tb2[k * 256 + j] * __ldg(Ew1 + j * 256 + t);
    g_cf[k * 256 + t] = a;
}

// fp32 W[kred][n] -> image: 8 k-slices x 32KB; atom (n>>3) 1KB; row (n&7) 128B
// = [hi k32 | lo k32] bf16, columns XOR-swizzled by (n&7)<<4.
__global__ void __launch_bounds__(256) prep_img(const float* __restrict__ Tw1,
                                                const float* __restrict__ Ew1,
                                                const float* __restrict__ Ew2)
{
    const int idx = blockIdx.x;
    const float* src;
    if (idx < 11)       src = Tw1 + (size_t)idx * 65536;
    else if (idx < 22)  src = g_Wf + (size_t)(idx - 11) * 65536;
    else if (idx == 22) src = Ew1;
    else                src = Ew2;
    char* img = (char*)g_wimg + (size_t)idx * 262144;

    const int lane = threadIdx.x & 31, wid = threadIdx.x >> 5;
    const int n = blockIdx.y * 32 + lane;
    for (int it = 0; it < 4; it++) {
        const int kc = (wid * 4 + it) * 8;
        float v[8];
#pragma unroll
        for (int i = 0; i < 8; i++) v[i] = __ldg(src + (size_t)(kc + i) * 256 + n);
        uint32_t hi[4], lo[4];
#pragma unroll
        for (int j = 0; j < 4; j++) {
            uint32_t p = pack_bf16x2(v[2 * j], v[2 * j + 1]);
            hi[j] = p;
            lo[j] = pack_bf16x2(v[2 * j] - lo16f(p), v[2 * j + 1] - hi16f(p));
        }
        uint32_t base = (uint32_t)((kc >> 5) * 32768 + (n >> 3) * 1024 + (n & 7) * 128);
        uint32_t msk = (uint32_t)(n & 7) << 4;
        uint32_t c = (uint32_t)(kc & 31) * 2u;
        *(uint4*)(img + base + (c ^ msk))        = make_uint4(hi[0], hi[1], hi[2], hi[3]);
        *(uint4*)(img + base + ((c + 64u) ^ msk)) = make_uint4(lo[0], lo[1], lo[2], lo[3]);
    }
}

// ---------------- scoring (1 warp per sample) ----------------
__global__ void __launch_bounds__(256) score_kernel(float* __restrict__ out)
{
    const int warp = threadIdx.x >> 5;
    const int lane = threadIdx.x & 31;
    const size_t b = (size_t)blockIdx.x * 8 + warp;

    float v[12][8];
    {
        const float4* p = (const float4*)(g_z + b * 256) + lane * 2;
        float4 u0 = p[0], u1 = p[1];
        v[0][0]=u0.x; v[0][1]=u0.y; v[0][2]=u0.z; v[0][3]=u0.w;
        v[0][4]=u1.x; v[0][5]=u1.y; v[0][6]=u1.z; v[0][7]=u1.w;
    }
#pragma unroll
    for (int k = 0; k < Kk; k++) {
        const float4* p = (const float4*)(g_zt + ((size_t)k * Bsz + b) * 256) + lane * 2;
        float4 u0 = p[0], u1 = p[1];
        v[1+k][0]=u0.x; v[1+k][1]=u0.y; v[1+k][2]=u0.z; v[1+k][3]=u0.w;
        v[1+k][4]=u1.x; v[1+k][5]=u1.y; v[1+k][6]=u1.z; v[1+k][7]=u1.w;
    }

    __shared__ float dots[8][80];
    int idx = 0;
#pragma unroll
    for (int p = 0; p < 12; p++) {
#pragma unroll
        for (int q = p; q < 12; q++) {
            float s = 0.f;
#pragma unroll
            for (int e = 0; e < 8; e++) s += v[p][e] * v[q][e];
#pragma unroll
            for (int off = 16; off; off >>= 1)
                s += __shfl_xor_sync(0xffffffffu, s, off);
            if (lane == 0) dots[warp][idx] = s;
            idx++;
        }
    }
    __syncwarp();

    auto pidx = [](int p, int q) {
        if (p > q) { int t = p; p = q; q = t; }
        return p * 12 - p * (p + 1) / 2 + q;
    };

    float score = 0.f;
    if (lane < Kk) {
        const float* d = dots[warp];
        const int kv = 1 + lane;
        float nz = sqrtf(d[pidx(0, 0)]);
        float nk = sqrtf(d[pidx(kv, kv)]);
        float simz = expf(d[pidx(0, kv)] / fmaxf(nz * nk, 1e-8f));
        float neg = 0.f;
        for (int l = 0; l < Kk; l++) {
            if (l == lane) continue;
            const int lv = 1 + l;
            float nl = sqrtf(d[pidx(lv, lv)]);
            neg += expf(d[pidx(lv, kv)] / fmaxf(nl * nk, 1e-8f));
        }
        score = logf(simz / (simz + neg));
    }
#pragma unroll
    for (int off = 16; off; off >>= 1)
        score += __shfl_xor_sync(0xffffffffu, score, off);
    if (lane == 0) out[b] = -score;
}

extern "C" void kernel_launch(void* const* d_in, const int* in_sizes, int n_in,
                              void* d_out, int out_size)
{
    const float* x   = (const float*)d_in[0];
    const float* Tw1 = (const float*)d_in[1];
    const float* Tb1 = (const float*)d_in[2];
    const float* Tw2 = (const float*)d_in[3];
    const float* Tb2 = (const float*)d_in[4];
    const float* Ew1 = (const float*)d_in[5];
    const float* Eb1 = (const float*)d_in[6];
    const float* Ew2 = (const float*)d_in[7];
    const float* Eb2 = (const float*)d_in[8];

    prep_wf<<<dim3(11, 8), 256>>>(Tw2, Ew1);
    prep_cf<<<11, 256>>>(Tb2, Ew1, Eb1);
    prep_img<<<dim3(24, 8), 256>>>(Tw1, Ew1, Ew2);

    cudaFuncSetAttribute(chain_kernel,
                         cudaFuncAttributeMaxDynamicSharedMemorySize, SM_TOTAL);
    chain_kernel<<<dim3(512, 12), 256, SM_TOTAL>>>(x, Tb1, Eb1, Eb2);

    score_kernel<<<Bsz / 8, 256>>>((float*)d_out);
}